// round 8
// baseline (speedup 1.0000x reference)
#include <cuda_runtime.h>
#include <cuda_bf16.h>
#include <math_constants.h>

#define NB     8
#define NQ     32
#define NTOK   1024
#define NDOCS  5000
#define DLEN   128
#define DIM    128
#define TOPK   100

// Scratch (no device allocation allowed)
__device__ int   g_flags[NB * NDOCS];
__device__ int   g_counts[NB];
__device__ int   g_upids[NB * NTOK];
__device__ float g_scores[NB * NTOK];

// ---------------------------------------------------------------- init
__global__ void init_kernel() {
    int i = blockIdx.x * blockDim.x + threadIdx.x;
    if (i < NB * NDOCS) g_flags[i] = 0;
    if (i < NB * NTOK) {
        g_scores[i] = -CUDART_INF_F;
        g_upids[i]  = -1;
    }
    if (i < NB) g_counts[i] = 0;
}

// ---------------------------------------------------------------- mark unique pids
// token_ids / emb2pid are INT32 (JAX x64 disabled downcasts int64 -> int32).
__global__ void mark_kernel(const int* __restrict__ token_ids,
                            const int* __restrict__ emb2pid) {
    int i = blockIdx.x * blockDim.x + threadIdx.x;
    if (i >= NB * NTOK) return;
    int b = i >> 10;  // NTOK = 1024
    int tok = token_ids[i];
    if (tok < 0 || tok >= NDOCS * DLEN) return;
    int pid = emb2pid[tok];
    if (pid < 0 || pid >= NDOCS) return;
    if (atomicExch(&g_flags[b * NDOCS + pid], 1) == 0) {
        int pos = atomicAdd(&g_counts[b], 1);
        g_upids[b * NTOK + pos] = pid;
    }
}

// ---------------------------------------------------------------- MaxSim score
// One block (128 threads) per (b, unique-pid). Thread t owns doc token t.
__global__ __launch_bounds__(DLEN) void score_kernel(
        const float* __restrict__ q_vectors,   // [NB, NQ, DIM]
        const float* __restrict__ vectors) {   // [NDOCS, DLEN, DIM]
    int b   = blockIdx.y;
    int idx = blockIdx.x;
    if (idx >= g_counts[b]) return;
    int pid = g_upids[b * NTOK + idx];

    __shared__ float qs[NQ * DIM];
    int tid = threadIdx.x;

    // load q[b] (32x128 f32 = 16KB) into smem, float4
    const float4* q4  = (const float4*)(q_vectors + (size_t)b * NQ * DIM);
    float4*       qs4 = (float4*)qs;
#pragma unroll
    for (int i = 0; i < (NQ * DIM / 4) / DLEN; i++)
        qs4[tid + i * DLEN] = q4[tid + i * DLEN];
    __syncthreads();

    const float4* v4p =
        (const float4*)(vectors + ((size_t)pid * DLEN + tid) * DIM);

    float dot[NQ];
#pragma unroll
    for (int q = 0; q < NQ; q++) dot[q] = 0.f;

#pragma unroll 4
    for (int h4 = 0; h4 < DIM / 4; h4++) {
        float4 v = v4p[h4];
#pragma unroll
        for (int q = 0; q < NQ; q++) {
            const float* qr = qs + q * DIM + h4 * 4;  // uniform -> smem broadcast
            dot[q] += v.x * qr[0] + v.y * qr[1] + v.z * qr[2] + v.w * qr[3];
        }
    }

    // max over doc tokens (128 threads, 4 warps), then sum over q
    int lane = tid & 31, warp = tid >> 5;
    __shared__ float wmax[4][NQ];
#pragma unroll
    for (int q = 0; q < NQ; q++) {
        float m = dot[q];
#pragma unroll
        for (int off = 16; off; off >>= 1)
            m = fmaxf(m, __shfl_xor_sync(0xffffffffu, m, off));
        if (lane == 0) wmax[warp][q] = m;
    }
    __syncthreads();
    if (warp == 0) {
        float m = fmaxf(fmaxf(wmax[0][lane], wmax[1][lane]),
                        fmaxf(wmax[2][lane], wmax[3][lane]));
#pragma unroll
        for (int off = 16; off; off >>= 1)
            m += __shfl_xor_sync(0xffffffffu, m, off);
        if (lane == 0) g_scores[b * NTOK + idx] = m;
    }
}

// ---------------------------------------------------------------- top-k
// One block (1024 threads) per batch row; 100 iterative block-argmax passes.
// Output layout (ALL float32): [NB*TOPK scores][NB*TOPK pids-as-float]
__global__ __launch_bounds__(NTOK) void topk_kernel(float* __restrict__ out) {
    int b = blockIdx.x, tid = threadIdx.x;
    float v = g_scores[b * NTOK + tid];

    __shared__ float sv[32];
    __shared__ int   si[32];
    __shared__ float bv;
    __shared__ int   bi;
    int lane = tid & 31, warp = tid >> 5;

    for (int kk = 0; kk < TOPK; kk++) {
        float mv = v;
        int   mi = tid;
#pragma unroll
        for (int off = 16; off; off >>= 1) {
            float ov = __shfl_xor_sync(0xffffffffu, mv, off);
            int   oi = __shfl_xor_sync(0xffffffffu, mi, off);
            if (ov > mv || (ov == mv && oi < mi)) { mv = ov; mi = oi; }
        }
        if (lane == 0) { sv[warp] = mv; si[warp] = mi; }
        __syncthreads();
        if (warp == 0) {
            mv = sv[lane]; mi = si[lane];
#pragma unroll
            for (int off = 16; off; off >>= 1) {
                float ov = __shfl_xor_sync(0xffffffffu, mv, off);
                int   oi = __shfl_xor_sync(0xffffffffu, mi, off);
                if (ov > mv || (ov == mv && oi < mi)) { mv = ov; mi = oi; }
            }
            if (lane == 0) { bv = mv; bi = mi; }
        }
        __syncthreads();
        if (tid == 0) {
            out[b * TOPK + kk]            = bv;
            out[NB * TOPK + b * TOPK + kk] = (float)g_upids[b * NTOK + bi];
        }
        if (tid == bi) v = -CUDART_INF_F;
        __syncthreads();
    }
}

// ---------------------------------------------------------------- launch
extern "C" void kernel_launch(void* const* d_in, const int* in_sizes, int n_in,
                              void* d_out, int out_size) {
    // identify inputs by element count (robust to metadata ordering)
    const float* q_vectors = nullptr;
    const int*   token_ids = nullptr;
    const float* vectors   = nullptr;
    const int*   emb2pid   = nullptr;
    for (int i = 0; i < n_in; i++) {
        long long sz = in_sizes[i];
        if (sz == NB * NQ * DIM)              q_vectors = (const float*)d_in[i];
        else if (sz == NB * NTOK)             token_ids = (const int*)d_in[i];
        else if (sz == (long long)NDOCS * DLEN * DIM) vectors = (const float*)d_in[i];
        else if (sz == (long long)NDOCS * DLEN)       emb2pid = (const int*)d_in[i];
        // k (size 1) is the compile-time TOPK
    }

    float* out = (float*)d_out;

    int init_n = NB * NDOCS;  // largest scratch array
    init_kernel<<<(init_n + 255) / 256, 256>>>();
    mark_kernel<<<(NB * NTOK + 255) / 256, 256>>>(token_ids, emb2pid);
    dim3 sgrid(NTOK, NB);
    score_kernel<<<sgrid, DLEN>>>(q_vectors, vectors);
    topk_kernel<<<NB, NTOK>>>(out);
    (void)out_size;
}

// round 9
// speedup vs baseline: 1.4867x; 1.4867x over previous
#include <cuda_runtime.h>
#include <cuda_bf16.h>
#include <math_constants.h>

#define NB     8
#define NQ     32
#define NTOK   1024
#define NDOCS  5000
#define DLEN   128
#define DIM    128
#define TOPK   100

// Scratch (no device allocation allowed)
__device__ int   g_flags[NB * NDOCS];
__device__ int   g_counts[NB];
__device__ int   g_upids[NB * NTOK];
__device__ float g_scores[NB * NTOK];

// ---------------------------------------------------------------- init
__global__ void init_kernel() {
    int i = blockIdx.x * blockDim.x + threadIdx.x;
    if (i < NB * NDOCS) g_flags[i] = 0;
    if (i < NB * NTOK) {
        g_scores[i] = -CUDART_INF_F;
        g_upids[i]  = -1;
    }
    if (i < NB) g_counts[i] = 0;
}

// ---------------------------------------------------------------- mark unique pids
// token_ids / emb2pid are INT32.
__global__ void mark_kernel(const int* __restrict__ token_ids,
                            const int* __restrict__ emb2pid) {
    int i = blockIdx.x * blockDim.x + threadIdx.x;
    if (i >= NB * NTOK) return;
    int b = i >> 10;  // NTOK = 1024
    int tok = token_ids[i];
    if (tok < 0 || tok >= NDOCS * DLEN) return;
    int pid = emb2pid[tok];
    if (pid < 0 || pid >= NDOCS) return;
    if (atomicExch(&g_flags[b * NDOCS + pid], 1) == 0) {
        int pos = atomicAdd(&g_counts[b], 1);
        g_upids[b * NTOK + pos] = pid;
    }
}

// ---------------------------------------------------------------- MaxSim score
// One block (128 threads) scores TWO docs. Thread t owns doc token t of both.
// One smem q read (LDS.128) feeds 8 FFMAs (4 dims x 2 pids).
__global__ __launch_bounds__(DLEN) void score_kernel(
        const float* __restrict__ q_vectors,   // [NB, NQ, DIM]
        const float* __restrict__ vectors) {   // [NDOCS, DLEN, DIM]
    int b    = blockIdx.y;
    int cnt  = g_counts[b];
    int idx0 = blockIdx.x * 2;
    if (idx0 >= cnt) return;
    int  idx1 = idx0 + 1;
    bool has1 = idx1 < cnt;
    int pid0 = g_upids[b * NTOK + idx0];
    int pid1 = has1 ? g_upids[b * NTOK + idx1] : pid0;

    __shared__ float qs[NQ * DIM];
    int tid = threadIdx.x;

    // load q[b] (32x128 f32 = 16KB) into smem, float4
    const float4* q4  = (const float4*)(q_vectors + (size_t)b * NQ * DIM);
    float4*       qs4 = (float4*)qs;
#pragma unroll
    for (int i = 0; i < (NQ * DIM / 4) / DLEN; i++)
        qs4[tid + i * DLEN] = q4[tid + i * DLEN];
    __syncthreads();

    const float4* v0p =
        (const float4*)(vectors + ((size_t)pid0 * DLEN + tid) * DIM);
    const float4* v1p =
        (const float4*)(vectors + ((size_t)pid1 * DLEN + tid) * DIM);

    float dot0[NQ], dot1[NQ];
#pragma unroll
    for (int q = 0; q < NQ; q++) { dot0[q] = 0.f; dot1[q] = 0.f; }

#pragma unroll 4
    for (int h4 = 0; h4 < DIM / 4; h4++) {
        float4 v0 = v0p[h4];
        float4 v1 = v1p[h4];
#pragma unroll
        for (int q = 0; q < NQ; q++) {
            float4 qv = *(const float4*)(qs + q * DIM + h4 * 4);  // warp-uniform -> broadcast
            dot0[q] += v0.x * qv.x + v0.y * qv.y + v0.z * qv.z + v0.w * qv.w;
            dot1[q] += v1.x * qv.x + v1.y * qv.y + v1.z * qv.z + v1.w * qv.w;
        }
    }

    // max over doc tokens (128 threads, 4 warps), then sum over q
    int lane = tid & 31, warp = tid >> 5;
    __shared__ float wmax[2][4][NQ];
#pragma unroll
    for (int q = 0; q < NQ; q++) {
        float m0 = dot0[q], m1 = dot1[q];
#pragma unroll
        for (int off = 16; off; off >>= 1) {
            m0 = fmaxf(m0, __shfl_xor_sync(0xffffffffu, m0, off));
            m1 = fmaxf(m1, __shfl_xor_sync(0xffffffffu, m1, off));
        }
        if (lane == 0) { wmax[0][warp][q] = m0; wmax[1][warp][q] = m1; }
    }
    __syncthreads();
    if (warp < 2) {  // warp 0 -> pid0, warp 1 -> pid1
        float m = fmaxf(fmaxf(wmax[warp][0][lane], wmax[warp][1][lane]),
                        fmaxf(wmax[warp][2][lane], wmax[warp][3][lane]));
#pragma unroll
        for (int off = 16; off; off >>= 1)
            m += __shfl_xor_sync(0xffffffffu, m, off);
        if (lane == 0) {
            if (warp == 0)      g_scores[b * NTOK + idx0] = m;
            else if (has1)      g_scores[b * NTOK + idx1] = m;
        }
    }
}

// ---------------------------------------------------------------- top-k
// Bitonic sort of 1024 packed 64-bit keys per row; keys pre-inverted so an
// ascending sort yields descending scores. Output: [800 f32 scores][800 f32 pids]
__global__ __launch_bounds__(NTOK) void topk_kernel(float* __restrict__ out) {
    __shared__ unsigned long long keys[NTOK];
    int b = blockIdx.x, tid = threadIdx.x;

    float s = g_scores[b * NTOK + tid];
    unsigned int bits = __float_as_uint(s);
    unsigned int u = (bits & 0x80000000u) ? ~bits : (bits | 0x80000000u);
    keys[tid] = ~(((unsigned long long)u << 32) | (unsigned int)tid);
    __syncthreads();

    for (int k = 2; k <= NTOK; k <<= 1) {
        for (int j = k >> 1; j > 0; j >>= 1) {
            int ixj = tid ^ j;
            if (ixj > tid) {
                unsigned long long a = keys[tid], c = keys[ixj];
                bool up = ((tid & k) == 0);
                if ((a > c) == up) { keys[tid] = c; keys[ixj] = a; }
            }
            __syncthreads();
        }
    }

    if (tid < TOPK) {
        int idx = (int)(~keys[tid] & 0xFFFFFFFFull);
        out[b * TOPK + tid]             = g_scores[b * NTOK + idx];
        out[NB * TOPK + b * TOPK + tid] = (float)g_upids[b * NTOK + idx];
    }
}

// ---------------------------------------------------------------- launch
extern "C" void kernel_launch(void* const* d_in, const int* in_sizes, int n_in,
                              void* d_out, int out_size) {
    // identify inputs by element count (robust to metadata ordering)
    const float* q_vectors = nullptr;
    const int*   token_ids = nullptr;
    const float* vectors   = nullptr;
    const int*   emb2pid   = nullptr;
    for (int i = 0; i < n_in; i++) {
        long long sz = in_sizes[i];
        if (sz == NB * NQ * DIM)              q_vectors = (const float*)d_in[i];
        else if (sz == NB * NTOK)             token_ids = (const int*)d_in[i];
        else if (sz == (long long)NDOCS * DLEN * DIM) vectors = (const float*)d_in[i];
        else if (sz == (long long)NDOCS * DLEN)       emb2pid = (const int*)d_in[i];
        // k (size 1) is the compile-time TOPK
    }

    float* out = (float*)d_out;

    int init_n = NB * NDOCS;  // largest scratch array
    init_kernel<<<(init_n + 255) / 256, 256>>>();
    mark_kernel<<<(NB * NTOK + 255) / 256, 256>>>(token_ids, emb2pid);
    dim3 sgrid(NTOK / 2, NB);
    score_kernel<<<sgrid, DLEN>>>(q_vectors, vectors);
    topk_kernel<<<NB, NTOK>>>(out);
    (void)out_size;
}